// round 2
// baseline (speedup 1.0000x reference)
#include <cuda_runtime.h>
#include <math.h>

// ---------------------------------------------------------------------------
// Problem constants
// ---------------------------------------------------------------------------
static constexpr int Bn   = 48;
static constexpr int Ln   = 512;
static constexpr int Dn   = 192;
static constexpr int Hn   = 6;
static constexpr int DKn  = 32;
static constexpr int HIDn = 768;
static constexpr int ROWS = Bn * Ln;              // 24576 token rows
static constexpr long long BLD = (long long)ROWS * Dn;      // 4,718,592
static constexpr long long SZ_S = (long long)Bn * Hn * Ln * Ln; // 75,497,472
static constexpr long long SZ_HID = (long long)ROWS * HIDn;     // 18,874,368
static constexpr float SCALE = 0.17677669529663689f;  // 1/sqrt(32)
static constexpr float EPSf  = 1e-5f;

// ---------------------------------------------------------------------------
// Static device scratch (allocation-free rule: __device__ globals only)
// ---------------------------------------------------------------------------
static constexpr long long N_BLD_BUFS = 15;
static constexpr long long WS_FLOATS = N_BLD_BUFS * BLD + SZ_S + SZ_HID;
__device__ float g_ws[WS_FLOATS];

// valid masks are 32-bit on disk (bool widened by the harness). Reading as
// unsigned int and testing !=0 is correct for both int32 (0x1) and
// float32 (0x3F800000) encodings of True.

// ---------------------------------------------------------------------------
// Masked LayerNorm (optionally fused residual add)
// One warp per row, 6 elements per lane (D=192).
// ---------------------------------------------------------------------------
__global__ void mln_kernel(const float* __restrict__ x,
                           const float* __restrict__ res,   // may be nullptr
                           const unsigned int* __restrict__ valid,
                           const float* __restrict__ gamma,
                           const float* __restrict__ beta,
                           float* __restrict__ out)
{
    int warp = threadIdx.x >> 5;
    int lane = threadIdx.x & 31;
    int row  = blockIdx.x * 8 + warp;

    const float* xr = x + (long long)row * Dn;
    float v[6];
    float s = 0.f;
#pragma unroll
    for (int e = 0; e < 6; e++) {
        int idx = lane + 32 * e;
        float t = xr[idx];
        if (res) t += res[(long long)row * Dn + idx];
        v[e] = t;
        s += t;
    }
    float s2 = 0.f;
#pragma unroll
    for (int e = 0; e < 6; e++) s2 += v[e] * v[e];
#pragma unroll
    for (int o = 16; o > 0; o >>= 1) {
        s  += __shfl_xor_sync(0xffffffffu, s,  o);
        s2 += __shfl_xor_sync(0xffffffffu, s2, o);
    }
    float mu   = s * (1.f / Dn);
    float var  = s2 * (1.f / Dn) - mu * mu;
    float rstd = rsqrtf(var + EPSf);
    bool ok = valid[row] != 0u;
#pragma unroll
    for (int e = 0; e < 6; e++) {
        int idx = lane + 32 * e;
        float o_ = ok ? fmaf((v[e] - mu) * rstd, gamma[idx], beta[idx]) : v[e];
        out[(long long)row * Dn + idx] = o_;
    }
}

// ---------------------------------------------------------------------------
// Generic GEMM  C[M,N] = A[M,K] @ W[K,N] + bias  (EPI=1: exact GELU epilogue)
// 64x64 tile, BK=16, 256 threads, 4x4 per-thread microtile.
// ---------------------------------------------------------------------------
template <int EPI>
__global__ void gemm64_kernel(const float* __restrict__ A,
                              const float* __restrict__ W,
                              const float* __restrict__ bias,
                              float* __restrict__ C,
                              int M, int N, int K)
{
    __shared__ float As[16][65];
    __shared__ float Bs[16][64];
    int bm = blockIdx.x * 64;
    int bn = blockIdx.y * 64;
    int tid = threadIdx.x;
    int tx = tid & 15, ty = tid >> 4;

    float acc[4][4] = {};

    for (int k0 = 0; k0 < K; k0 += 16) {
#pragma unroll
        for (int i = 0; i < 4; i++) {
            int id = tid + i * 256;
            int kk = id & 15, mm = id >> 4;          // A: [64 rows][16 k]
            As[kk][mm] = A[(long long)(bm + mm) * K + k0 + kk];
            int nn = id & 63, kb = id >> 6;          // W: [16 k][64 n]
            Bs[kb][nn] = W[(long long)(k0 + kb) * N + bn + nn];
        }
        __syncthreads();
#pragma unroll
        for (int k = 0; k < 16; k++) {
            float af[4], bf[4];
#pragma unroll
            for (int i = 0; i < 4; i++) af[i] = As[k][ty * 4 + i];
#pragma unroll
            for (int j = 0; j < 4; j++) bf[j] = Bs[k][tx * 4 + j];
#pragma unroll
            for (int i = 0; i < 4; i++)
#pragma unroll
                for (int j = 0; j < 4; j++)
                    acc[i][j] = fmaf(af[i], bf[j], acc[i][j]);
        }
        __syncthreads();
    }

#pragma unroll
    for (int i = 0; i < 4; i++) {
        int m = bm + ty * 4 + i;
#pragma unroll
        for (int j = 0; j < 4; j++) {
            int n = bn + tx * 4 + j;
            float c = acc[i][j] + bias[n];
            if (EPI == 1) c = c * normcdff(c);  // exact GELU: x * Phi(x)
            C[(long long)m * N + n] = c;
        }
    }
}

// ---------------------------------------------------------------------------
// Attention scores: S[bh, m, n] = SCALE * Q[b,m,h,:] . K[b,n,h,:]; mask -> -1e9
// ---------------------------------------------------------------------------
__global__ void score_kernel(const float* __restrict__ Q,
                             const float* __restrict__ Kp,
                             const unsigned int* __restrict__ vq,
                             const unsigned int* __restrict__ vk,
                             float* __restrict__ S)
{
    __shared__ float Qs[32][65];
    __shared__ float Ks[32][65];
    __shared__ unsigned char vqs[64], vks[64];

    int bh = blockIdx.z;
    int b = bh / Hn, h = bh % Hn;
    int bm = blockIdx.x * 64, bn = blockIdx.y * 64;
    int tid = threadIdx.x;

    const float* Qb = Q  + (long long)b * Ln * Dn + h * DKn;
    const float* Kb = Kp + (long long)b * Ln * Dn + h * DKn;

#pragma unroll
    for (int i = 0; i < 8; i++) {
        int id = tid + i * 256;
        int d = id & 31, r = id >> 5;  // r in [0,64)
        Qs[d][r] = Qb[(long long)(bm + r) * Dn + d];
        Ks[d][r] = Kb[(long long)(bn + r) * Dn + d];
    }
    if (tid < 64)            vqs[tid]      = (vq[b * Ln + bm + tid] != 0u) ? 1 : 0;
    else if (tid < 128)      vks[tid - 64] = (vk[b * Ln + bn + tid - 64] != 0u) ? 1 : 0;
    __syncthreads();

    int tx = tid & 15, ty = tid >> 4;
    float acc[4][4] = {};
#pragma unroll
    for (int k = 0; k < 32; k++) {
        float af[4], bf[4];
#pragma unroll
        for (int i = 0; i < 4; i++) af[i] = Qs[k][ty * 4 + i];
#pragma unroll
        for (int j = 0; j < 4; j++) bf[j] = Ks[k][tx * 4 + j];
#pragma unroll
        for (int i = 0; i < 4; i++)
#pragma unroll
            for (int j = 0; j < 4; j++)
                acc[i][j] = fmaf(af[i], bf[j], acc[i][j]);
    }

    float* Sb = S + (long long)bh * Ln * Ln;
#pragma unroll
    for (int i = 0; i < 4; i++) {
        int m = bm + ty * 4 + i;
#pragma unroll
        for (int j = 0; j < 4; j++) {
            int n = bn + tx * 4 + j;
            float s = acc[i][j] * SCALE;
            if (!(vqs[ty * 4 + i] && vks[tx * 4 + j])) s = -1e9f;
            Sb[(long long)m * Ln + n] = s;
        }
    }
}

// ---------------------------------------------------------------------------
// In-place row softmax over width 512. One warp per row, 16 elems/lane.
// ---------------------------------------------------------------------------
__global__ void softmax_kernel(float* __restrict__ S)
{
    int warp = threadIdx.x >> 5;
    int lane = threadIdx.x & 31;
    long long row = (long long)blockIdx.x * 8 + warp;
    float* p = S + row * Ln;

    float v[16];
    float mx = -INFINITY;
#pragma unroll
    for (int t = 0; t < 16; t++) {
        v[t] = p[lane + 32 * t];
        mx = fmaxf(mx, v[t]);
    }
#pragma unroll
    for (int o = 16; o > 0; o >>= 1)
        mx = fmaxf(mx, __shfl_xor_sync(0xffffffffu, mx, o));
    float s = 0.f;
#pragma unroll
    for (int t = 0; t < 16; t++) {
        v[t] = __expf(v[t] - mx);
        s += v[t];
    }
#pragma unroll
    for (int o = 16; o > 0; o >>= 1)
        s += __shfl_xor_sync(0xffffffffu, s, o);
    float inv = 1.f / s;
#pragma unroll
    for (int t = 0; t < 16; t++)
        p[lane + 32 * t] = v[t] * inv;
}

// ---------------------------------------------------------------------------
// ctx[b, m, h*32 + d] = sum_j P[bh, m, j] * V[b, j, h*32 + d]
// ---------------------------------------------------------------------------
__global__ void pv_kernel(const float* __restrict__ P,
                          const float* __restrict__ V,
                          float* __restrict__ ctx)
{
    __shared__ float Ps[32][65];
    __shared__ float Vs[32][33];
    int bh = blockIdx.z;
    int b = bh / Hn, h = bh % Hn;
    int bm = blockIdx.x * 64;
    int tid = threadIdx.x;
    int tx = tid & 15, ty = tid >> 4;

    const float* Pb = P + ((long long)bh * Ln + bm) * Ln;
    const float* Vb = V + (long long)b * Ln * Dn + h * DKn;

    float acc[4][2] = {};
    for (int k0 = 0; k0 < Ln; k0 += 32) {
#pragma unroll
        for (int i = 0; i < 8; i++) {
            int id = tid + i * 256;
            int kk = id & 31, mm = id >> 5;
            Ps[kk][mm] = Pb[(long long)mm * Ln + k0 + kk];
        }
#pragma unroll
        for (int i = 0; i < 4; i++) {
            int id = tid + i * 256;
            int nn = id & 31, kk = id >> 5;
            Vs[kk][nn] = Vb[(long long)(k0 + kk) * Dn + nn];
        }
        __syncthreads();
#pragma unroll
        for (int k = 0; k < 32; k++) {
            float af[4], bf[2];
#pragma unroll
            for (int i = 0; i < 4; i++) af[i] = Ps[k][ty * 4 + i];
            bf[0] = Vs[k][tx * 2];
            bf[1] = Vs[k][tx * 2 + 1];
#pragma unroll
            for (int i = 0; i < 4; i++) {
                acc[i][0] = fmaf(af[i], bf[0], acc[i][0]);
                acc[i][1] = fmaf(af[i], bf[1], acc[i][1]);
            }
        }
        __syncthreads();
    }

#pragma unroll
    for (int i = 0; i < 4; i++) {
        long long m = (long long)b * Ln + bm + ty * 4 + i;
#pragma unroll
        for (int j = 0; j < 2; j++)
            ctx[m * Dn + h * DKn + tx * 2 + j] = acc[i][j];
    }
}

// ---------------------------------------------------------------------------
// Host launcher
// ---------------------------------------------------------------------------
extern "C" void kernel_launch(void* const* d_in, const int* in_sizes, int n_in,
                              void* d_out, int out_size)
{
    const float* x_a = (const float*)d_in[0];
    const float* x_b = (const float*)d_in[1];
    const unsigned int* valid_a = (const unsigned int*)d_in[2];
    const unsigned int* valid_b = (const unsigned int*)d_in[3];
    const float* ln_a_g  = (const float*)d_in[4];
    const float* ln_a_b  = (const float*)d_in[5];
    const float* ln_b_g  = (const float*)d_in[6];
    const float* ln_b_b  = (const float*)d_in[7];
    const float* ln_oa_g = (const float*)d_in[8];
    const float* ln_oa_b = (const float*)d_in[9];
    const float* ln_ob_g = (const float*)d_in[10];
    const float* ln_ob_b = (const float*)d_in[11];
    const float* wq = (const float*)d_in[12];
    const float* bq = (const float*)d_in[13];
    const float* wk = (const float*)d_in[14];
    const float* bk = (const float*)d_in[15];
    const float* wv = (const float*)d_in[16];
    const float* bv = (const float*)d_in[17];
    const float* wo = (const float*)d_in[18];
    const float* bo = (const float*)d_in[19];
    const float* fln_g  = (const float*)d_in[20];
    const float* fln_b  = (const float*)d_in[21];
    const float* flno_g = (const float*)d_in[22];
    const float* flno_b = (const float*)d_in[23];
    const float* w1 = (const float*)d_in[24];
    const float* b1 = (const float*)d_in[25];
    const float* w2 = (const float*)d_in[26];
    const float* b2 = (const float*)d_in[27];

    float* ws = nullptr;
    cudaGetSymbolAddress((void**)&ws, g_ws);

    float* aln  = ws + 0 * BLD;
    float* bln  = ws + 1 * BLD;
    float* Qa   = ws + 2 * BLD;
    float* Ka   = ws + 3 * BLD;
    float* Va   = ws + 4 * BLD;
    float* Qb   = ws + 5 * BLD;
    float* Kb   = ws + 6 * BLD;
    float* Vb   = ws + 7 * BLD;
    float* ctxa = ws + 8 * BLD;
    float* ctxb = ws + 9 * BLD;
    float* tmp  = ws + 10 * BLD;
    float* oa   = ws + 11 * BLD;
    float* ob   = ws + 12 * BLD;
    float* xn   = ws + 13 * BLD;
    float* yb   = ws + 14 * BLD;
    float* Sbuf = ws + 15 * BLD;
    float* hid  = Sbuf + SZ_S;

    float* out_a = (float*)d_out;
    float* out_b = (float*)d_out + BLD;

    dim3 blk(256);
    dim3 gLN(ROWS / 8);                 // 3072
    dim3 gProj(ROWS / 64, Dn / 64);     // 384 x 3
    dim3 gW1(ROWS / 64, HIDn / 64);     // 384 x 12
    dim3 gScore(Ln / 64, Ln / 64, Bn * Hn);  // 8 x 8 x 288
    dim3 gSm(Bn * Hn * Ln / 8);         // 18432
    dim3 gPV(Ln / 64, 1, Bn * Hn);      // 8 x 1 x 288

    // 1. pre-attention masked LN
    mln_kernel<<<gLN, blk>>>(x_a, nullptr, valid_a, ln_a_g, ln_a_b, aln);
    mln_kernel<<<gLN, blk>>>(x_b, nullptr, valid_b, ln_b_g, ln_b_b, bln);

    // 2. six projections (shared weights)
    gemm64_kernel<0><<<gProj, blk>>>(aln, wq, bq, Qa, ROWS, Dn, Dn);
    gemm64_kernel<0><<<gProj, blk>>>(aln, wk, bk, Ka, ROWS, Dn, Dn);
    gemm64_kernel<0><<<gProj, blk>>>(aln, wv, bv, Va, ROWS, Dn, Dn);
    gemm64_kernel<0><<<gProj, blk>>>(bln, wq, bq, Qb, ROWS, Dn, Dn);
    gemm64_kernel<0><<<gProj, blk>>>(bln, wk, bk, Kb, ROWS, Dn, Dn);
    gemm64_kernel<0><<<gProj, blk>>>(bln, wv, bv, Vb, ROWS, Dn, Dn);

    // 3. attention a <- b
    score_kernel<<<gScore, blk>>>(Qa, Kb, valid_a, valid_b, Sbuf);
    softmax_kernel<<<gSm, blk>>>(Sbuf);
    pv_kernel<<<gPV, blk>>>(Sbuf, Vb, ctxa);

    // 4. attention b <- a (re-uses S scratch)
    score_kernel<<<gScore, blk>>>(Qb, Ka, valid_b, valid_a, Sbuf);
    softmax_kernel<<<gSm, blk>>>(Sbuf);
    pv_kernel<<<gPV, blk>>>(Sbuf, Va, ctxb);

    // 5. output projection + residual + masked LN
    gemm64_kernel<0><<<gProj, blk>>>(ctxa, wo, bo, tmp, ROWS, Dn, Dn);
    mln_kernel<<<gLN, blk>>>(tmp, x_a, valid_a, ln_oa_g, ln_oa_b, oa);
    gemm64_kernel<0><<<gProj, blk>>>(ctxb, wo, bo, tmp, ROWS, Dn, Dn);
    mln_kernel<<<gLN, blk>>>(tmp, x_b, valid_b, ln_ob_g, ln_ob_b, ob);

    // 6. FFN for a
    mln_kernel<<<gLN, blk>>>(oa, nullptr, valid_a, fln_g, fln_b, xn);
    gemm64_kernel<1><<<gW1, blk>>>(xn, w1, b1, hid, ROWS, HIDn, Dn);
    gemm64_kernel<0><<<gProj, blk>>>(hid, w2, b2, yb, ROWS, Dn, HIDn);
    mln_kernel<<<gLN, blk>>>(yb, oa, valid_a, flno_g, flno_b, out_a);

    // 7. FFN for b
    mln_kernel<<<gLN, blk>>>(ob, nullptr, valid_b, fln_g, fln_b, xn);
    gemm64_kernel<1><<<gW1, blk>>>(xn, w1, b1, hid, ROWS, HIDn, Dn);
    gemm64_kernel<0><<<gProj, blk>>>(hid, w2, b2, yb, ROWS, Dn, HIDn);
    mln_kernel<<<gLN, blk>>>(yb, ob, valid_b, flno_g, flno_b, out_b);
}

// round 3
// speedup vs baseline: 1.3983x; 1.3983x over previous
#include <cuda_runtime.h>
#include <math.h>

// ---------------------------------------------------------------------------
// Problem constants
// ---------------------------------------------------------------------------
static constexpr int Bn   = 48;
static constexpr int Ln   = 512;
static constexpr int Dn   = 192;
static constexpr int Hn   = 6;
static constexpr int DKn  = 32;
static constexpr int HIDn = 768;
static constexpr int ROWS = Bn * Ln;                         // 24576
static constexpr long long BLD = (long long)ROWS * Dn;       // 4,718,592
static constexpr long long SZ_HID = (long long)ROWS * HIDn;  // 18,874,368
static constexpr float SCALE = 0.17677669529663689f;         // 1/sqrt(32)
static constexpr float EPSf  = 1e-5f;

// ---------------------------------------------------------------------------
// Static device scratch
// ---------------------------------------------------------------------------
static constexpr long long WS_FLOATS = 15 * BLD + SZ_HID;
__device__ float g_ws[WS_FLOATS];

// ---------------------------------------------------------------------------
// f32x2 packed helpers (sm_103a FFMA2 path)
// ---------------------------------------------------------------------------
typedef unsigned long long ull;

__device__ __forceinline__ ull pk2(float lo, float hi) {
    ull r; asm("mov.b64 %0, {%1,%2};" : "=l"(r) : "f"(lo), "f"(hi)); return r;
}
__device__ __forceinline__ void upk2(ull v, float& lo, float& hi) {
    asm("mov.b64 {%0,%1}, %2;" : "=f"(lo), "=f"(hi) : "l"(v));
}
__device__ __forceinline__ ull ffma2(ull a, ull b, ull c) {
    ull d; asm("fma.rn.f32x2 %0, %1, %2, %3;" : "=l"(d) : "l"(a), "l"(b), "l"(c)); return d;
}
__device__ __forceinline__ ull fmul2(ull a, ull b) {
    ull d; asm("mul.rn.f32x2 %0, %1, %2;" : "=l"(d) : "l"(a), "l"(b)); return d;
}

// ---------------------------------------------------------------------------
// Masked LayerNorm (optional fused residual). One warp per row.
// ---------------------------------------------------------------------------
__global__ void mln_kernel(const float* __restrict__ x,
                           const float* __restrict__ res,
                           const unsigned int* __restrict__ valid,
                           const float* __restrict__ gamma,
                           const float* __restrict__ beta,
                           float* __restrict__ out)
{
    int warp = threadIdx.x >> 5;
    int lane = threadIdx.x & 31;
    int row  = blockIdx.x * 8 + warp;

    const float* xr = x + (long long)row * Dn;
    float v[6];
    float s = 0.f;
#pragma unroll
    for (int e = 0; e < 6; e++) {
        int idx = lane + 32 * e;
        float t = xr[idx];
        if (res) t += res[(long long)row * Dn + idx];
        v[e] = t;
        s += t;
    }
    float s2 = 0.f;
#pragma unroll
    for (int e = 0; e < 6; e++) s2 += v[e] * v[e];
#pragma unroll
    for (int o = 16; o > 0; o >>= 1) {
        s  += __shfl_xor_sync(0xffffffffu, s,  o);
        s2 += __shfl_xor_sync(0xffffffffu, s2, o);
    }
    float mu   = s * (1.f / Dn);
    float var  = s2 * (1.f / Dn) - mu * mu;
    float rstd = rsqrtf(var + EPSf);
    bool ok = valid[row] != 0u;
#pragma unroll
    for (int e = 0; e < 6; e++) {
        int idx = lane + 32 * e;
        float o_ = ok ? fmaf((v[e] - mu) * rstd, gamma[idx], beta[idx]) : v[e];
        out[(long long)row * Dn + idx] = o_;
    }
}

// ---------------------------------------------------------------------------
// FFMA2 GEMM: C[M,N] = A[M,K] @ W[K,N] + bias, EPI=1: exact GELU.
// Tile 128x64, BK=16, 256 threads, microtile 8 rows x 4 cols (2 f32x2 pairs),
// register-staged double-buffered smem.
// ---------------------------------------------------------------------------
template <int EPI>
__global__ __launch_bounds__(256) void gemm_f2_kernel(
    const float* __restrict__ A, const float* __restrict__ W,
    const float* __restrict__ bias, float* __restrict__ C,
    int M, int N, int K)
{
    __shared__ float As[2][16][136];   // [buf][k][m]
    __shared__ float Bs[2][16][68];    // [buf][k][n]

    const int tid = threadIdx.x;
    const int tx = tid & 15, ty = tid >> 4;
    const int bm = blockIdx.x * 128, bn = blockIdx.y * 64;

    const int arow = tid >> 1, ak = (tid & 1) * 8;   // A: 2 thr/row, 8 k each
    const int bk   = tid >> 4, bc = (tid & 15) * 4;  // B: row k, 4 cols

    const float* gA = A + (long long)(bm + arow) * K + ak;
    const float* gB = W + (long long)bk * N + bn + bc;

    float ar[8];
    float4 bstage;

    // prologue: tile 0 -> buf 0
    {
        *(float4*)&ar[0] = *(const float4*)(gA);
        *(float4*)&ar[4] = *(const float4*)(gA + 4);
        bstage = *(const float4*)(gB);
#pragma unroll
        for (int c = 0; c < 8; c++) As[0][ak + c][arow] = ar[c];
        *(float4*)&Bs[0][bk][bc] = bstage;
    }

    ull acc0[8], acc1[8];
#pragma unroll
    for (int i = 0; i < 8; i++) { acc0[i] = 0ull; acc1[i] = 0ull; }

    const int T = K >> 4;
    for (int t = 0; t < T; t++) {
        __syncthreads();
        const int buf = t & 1;
        if (t + 1 < T) {
            *(float4*)&ar[0] = *(const float4*)(gA + (t + 1) * 16);
            *(float4*)&ar[4] = *(const float4*)(gA + (t + 1) * 16 + 4);
            bstage = *(const float4*)(gB + (long long)(t + 1) * 16 * N);
        }
#pragma unroll
        for (int k = 0; k < 16; k++) {
            float av[8];
            *(float4*)&av[0] = *(const float4*)&As[buf][k][ty * 8];
            *(float4*)&av[4] = *(const float4*)&As[buf][k][ty * 8 + 4];
            const ull* bp = (const ull*)&Bs[buf][k][tx * 4];
            ull b01 = bp[0], b23 = bp[1];
#pragma unroll
            for (int i = 0; i < 8; i++) {
                ull a2 = pk2(av[i], av[i]);
                acc0[i] = ffma2(a2, b01, acc0[i]);
                acc1[i] = ffma2(a2, b23, acc1[i]);
            }
        }
        if (t + 1 < T) {
            const int nb = buf ^ 1;
#pragma unroll
            for (int c = 0; c < 8; c++) As[nb][ak + c][arow] = ar[c];
            *(float4*)&Bs[nb][bk][bc] = bstage;
        }
    }

    float4 b4 = *(const float4*)(bias + bn + tx * 4);
#pragma unroll
    for (int i = 0; i < 8; i++) {
        float c0, c1, c2, c3;
        upk2(acc0[i], c0, c1);
        upk2(acc1[i], c2, c3);
        c0 += b4.x; c1 += b4.y; c2 += b4.z; c3 += b4.w;
        if (EPI == 1) {
            c0 *= normcdff(c0); c1 *= normcdff(c1);
            c2 *= normcdff(c2); c3 *= normcdff(c3);
        }
        float4 o = make_float4(c0, c1, c2, c3);
        *(float4*)(C + (long long)(bm + ty * 8 + i) * N + bn + tx * 4) = o;
    }
}

// ---------------------------------------------------------------------------
// Flash attention: per block = (q-tile of 64, b*h). Online softmax, no S buffer.
// ctx[b, m, h*32+d] = softmax(scale*Q.K^T with mask)[m,:] @ V
// ---------------------------------------------------------------------------
__global__ __launch_bounds__(256) void flash_kernel(
    const float* __restrict__ Q, const float* __restrict__ Kp,
    const float* __restrict__ V,
    const unsigned int* __restrict__ vq, const unsigned int* __restrict__ vk,
    float* __restrict__ ctx)
{
    __shared__ float Qs[32][68];   // [d][m], Q pre-scaled
    __shared__ float Ks[32][68];   // [d][n]
    __shared__ float Vs[64][34];   // [j][d]
    __shared__ float Ps[64][68];   // [m][j]
    __shared__ unsigned char vqs[64];
    __shared__ unsigned char vks[64];

    const int tid = threadIdx.x;
    const int tx = tid & 15, ty = tid >> 4;
    const int qt = blockIdx.x;
    const int bh = blockIdx.y;
    const int b = bh / Hn, h = bh % Hn;

    const float* Qb = Q  + (long long)b * Ln * Dn + h * DKn;
    const float* Kb = Kp + (long long)b * Ln * Dn + h * DKn;
    const float* Vb = V  + (long long)b * Ln * Dn + h * DKn;

    const int ld = tid & 31, lr = tid >> 5;   // loader: d, row-base

    // Q tile (scaled) + K/V tile 0 + masks
#pragma unroll
    for (int i = 0; i < 8; i++) {
        int r = lr + i * 8;
        Qs[ld][r] = Qb[(long long)(qt * 64 + r) * Dn + ld] * SCALE;
        Ks[ld][r] = Kb[(long long)r * Dn + ld];
        Vs[r][ld] = Vb[(long long)r * Dn + ld];
    }
    if (tid < 64)       vqs[tid]      = (vq[b * Ln + qt * 64 + tid] != 0u) ? 1 : 0;
    else if (tid < 128) vks[tid - 64] = (vk[b * Ln + tid - 64]      != 0u) ? 1 : 0;
    __syncthreads();

    ull   o2[4]   = {0ull, 0ull, 0ull, 0ull};
    float mrow[4] = {-INFINITY, -INFINITY, -INFINITY, -INFINITY};
    float lrow[4] = {0.f, 0.f, 0.f, 0.f};

    float kreg[8], vreg[8];
    unsigned int vkr = 0u;

    for (int t = 0; t < 8; t++) {
        // ---- S = (scaled Q) K^T on this tile ----
        ull s01[4] = {0ull, 0ull, 0ull, 0ull};
        ull s23[4] = {0ull, 0ull, 0ull, 0ull};
#pragma unroll
        for (int k = 0; k < 32; k++) {
            float4 aq = *(const float4*)&Qs[k][ty * 4];
            const ull* bp = (const ull*)&Ks[k][tx * 4];
            ull b01 = bp[0], b23 = bp[1];
            ull a;
            a = pk2(aq.x, aq.x); s01[0] = ffma2(a, b01, s01[0]); s23[0] = ffma2(a, b23, s23[0]);
            a = pk2(aq.y, aq.y); s01[1] = ffma2(a, b01, s01[1]); s23[1] = ffma2(a, b23, s23[1]);
            a = pk2(aq.z, aq.z); s01[2] = ffma2(a, b01, s01[2]); s23[2] = ffma2(a, b23, s23[2]);
            a = pk2(aq.w, aq.w); s01[3] = ffma2(a, b01, s01[3]); s23[3] = ffma2(a, b23, s23[3]);
        }

        // ---- prefetch next K/V tile into registers ----
        if (t < 7) {
#pragma unroll
            for (int i = 0; i < 8; i++) {
                int r = (t + 1) * 64 + lr + i * 8;
                kreg[i] = Kb[(long long)r * Dn + ld];
                vreg[i] = Vb[(long long)r * Dn + ld];
            }
            if (tid < 64) vkr = vk[b * Ln + (t + 1) * 64 + tid];
        }

        // ---- mask + online softmax ----
        float s[4][4];
#pragma unroll
        for (int i = 0; i < 4; i++) {
            upk2(s01[i], s[i][0], s[i][1]);
            upk2(s23[i], s[i][2], s[i][3]);
            bool qok = vqs[ty * 4 + i] != 0;
#pragma unroll
            for (int j = 0; j < 4; j++)
                if (!(qok && vks[tx * 4 + j])) s[i][j] = -1e9f;
        }
#pragma unroll
        for (int i = 0; i < 4; i++) {
            float tm = fmaxf(fmaxf(s[i][0], s[i][1]), fmaxf(s[i][2], s[i][3]));
#pragma unroll
            for (int o = 8; o > 0; o >>= 1)
                tm = fmaxf(tm, __shfl_xor_sync(0xffffffffu, tm, o));
            float nm = fmaxf(mrow[i], tm);
            float p0 = __expf(s[i][0] - nm);
            float p1 = __expf(s[i][1] - nm);
            float p2 = __expf(s[i][2] - nm);
            float p3 = __expf(s[i][3] - nm);
            float ts = (p0 + p1) + (p2 + p3);
#pragma unroll
            for (int o = 8; o > 0; o >>= 1)
                ts += __shfl_xor_sync(0xffffffffu, ts, o);
            float fac = __expf(mrow[i] - nm);
            lrow[i] = lrow[i] * fac + ts;
            mrow[i] = nm;
            o2[i] = fmul2(o2[i], pk2(fac, fac));
            float4 pv = make_float4(p0, p1, p2, p3);
            *(float4*)&Ps[ty * 4 + i][tx * 4] = pv;
        }
        __syncthreads();   // Ps ready; all reads of Ks done

        // ---- O += P @ V ----
#pragma unroll 4
        for (int j = 0; j < 64; j++) {
            ull v2 = *(const ull*)&Vs[j][tx * 2];
#pragma unroll
            for (int i = 0; i < 4; i++) {
                float p = Ps[ty * 4 + i][j];
                o2[i] = ffma2(pk2(p, p), v2, o2[i]);
            }
        }
        __syncthreads();   // all reads of Vs / Ps done

        if (t < 7) {
#pragma unroll
            for (int i = 0; i < 8; i++) {
                int r = lr + i * 8;
                Ks[ld][r] = kreg[i];
                Vs[r][ld] = vreg[i];
            }
            if (tid < 64) vks[tid] = (vkr != 0u) ? 1 : 0;
            __syncthreads();  // new K/V tile visible
        }
    }

    // ---- finalize ----
#pragma unroll
    for (int i = 0; i < 4; i++) {
        float o0, o1;
        upk2(o2[i], o0, o1);
        float inv = 1.f / lrow[i];
        long long row = (long long)b * Ln + qt * 64 + ty * 4 + i;
        float2 st = make_float2(o0 * inv, o1 * inv);
        *(float2*)(ctx + row * Dn + h * DKn + tx * 2) = st;
    }
}

// ---------------------------------------------------------------------------
// Host launcher
// ---------------------------------------------------------------------------
extern "C" void kernel_launch(void* const* d_in, const int* in_sizes, int n_in,
                              void* d_out, int out_size)
{
    const float* x_a = (const float*)d_in[0];
    const float* x_b = (const float*)d_in[1];
    const unsigned int* valid_a = (const unsigned int*)d_in[2];
    const unsigned int* valid_b = (const unsigned int*)d_in[3];
    const float* ln_a_g  = (const float*)d_in[4];
    const float* ln_a_b  = (const float*)d_in[5];
    const float* ln_b_g  = (const float*)d_in[6];
    const float* ln_b_b  = (const float*)d_in[7];
    const float* ln_oa_g = (const float*)d_in[8];
    const float* ln_oa_b = (const float*)d_in[9];
    const float* ln_ob_g = (const float*)d_in[10];
    const float* ln_ob_b = (const float*)d_in[11];
    const float* wq = (const float*)d_in[12];
    const float* bq = (const float*)d_in[13];
    const float* wk = (const float*)d_in[14];
    const float* bk = (const float*)d_in[15];
    const float* wv = (const float*)d_in[16];
    const float* bv = (const float*)d_in[17];
    const float* wo = (const float*)d_in[18];
    const float* bo = (const float*)d_in[19];
    const float* fln_g  = (const float*)d_in[20];
    const float* fln_b  = (const float*)d_in[21];
    const float* flno_g = (const float*)d_in[22];
    const float* flno_b = (const float*)d_in[23];
    const float* w1 = (const float*)d_in[24];
    const float* b1 = (const float*)d_in[25];
    const float* w2 = (const float*)d_in[26];
    const float* b2 = (const float*)d_in[27];

    float* ws = nullptr;
    cudaGetSymbolAddress((void**)&ws, g_ws);

    float* aln  = ws + 0 * BLD;
    float* bln  = ws + 1 * BLD;
    float* Qa   = ws + 2 * BLD;
    float* Ka   = ws + 3 * BLD;
    float* Va   = ws + 4 * BLD;
    float* Qb   = ws + 5 * BLD;
    float* Kb   = ws + 6 * BLD;
    float* Vb   = ws + 7 * BLD;
    float* ctxa = ws + 8 * BLD;
    float* ctxb = ws + 9 * BLD;
    float* tmp  = ws + 10 * BLD;
    float* oa   = ws + 11 * BLD;
    float* ob   = ws + 12 * BLD;
    float* xn   = ws + 13 * BLD;
    float* yb   = ws + 14 * BLD;
    float* hid  = ws + 15 * BLD;

    float* out_a = (float*)d_out;
    float* out_b = (float*)d_out + BLD;

    dim3 blk(256);
    dim3 gLN(ROWS / 8);                       // 3072
    dim3 gProj(ROWS / 128, Dn / 64);          // 192 x 3
    dim3 gW1(ROWS / 128, HIDn / 64);          // 192 x 12
    dim3 gFl(Ln / 64, Bn * Hn);               // 8 x 288

    // 1. pre-attention masked LN
    mln_kernel<<<gLN, blk>>>(x_a, nullptr, valid_a, ln_a_g, ln_a_b, aln);
    mln_kernel<<<gLN, blk>>>(x_b, nullptr, valid_b, ln_b_g, ln_b_b, bln);

    // 2. six projections (shared weights)
    gemm_f2_kernel<0><<<gProj, blk>>>(aln, wq, bq, Qa, ROWS, Dn, Dn);
    gemm_f2_kernel<0><<<gProj, blk>>>(aln, wk, bk, Ka, ROWS, Dn, Dn);
    gemm_f2_kernel<0><<<gProj, blk>>>(aln, wv, bv, Va, ROWS, Dn, Dn);
    gemm_f2_kernel<0><<<gProj, blk>>>(bln, wq, bq, Qb, ROWS, Dn, Dn);
    gemm_f2_kernel<0><<<gProj, blk>>>(bln, wk, bk, Kb, ROWS, Dn, Dn);
    gemm_f2_kernel<0><<<gProj, blk>>>(bln, wv, bv, Vb, ROWS, Dn, Dn);

    // 3. fused attention (both directions)
    flash_kernel<<<gFl, blk>>>(Qa, Kb, Vb, valid_a, valid_b, ctxa);
    flash_kernel<<<gFl, blk>>>(Qb, Ka, Va, valid_b, valid_a, ctxb);

    // 4. output projection + residual + masked LN
    gemm_f2_kernel<0><<<gProj, blk>>>(ctxa, wo, bo, tmp, ROWS, Dn, Dn);
    mln_kernel<<<gLN, blk>>>(tmp, x_a, valid_a, ln_oa_g, ln_oa_b, oa);
    gemm_f2_kernel<0><<<gProj, blk>>>(ctxb, wo, bo, tmp, ROWS, Dn, Dn);
    mln_kernel<<<gLN, blk>>>(tmp, x_b, valid_b, ln_ob_g, ln_ob_b, ob);

    // 5. FFN for a
    mln_kernel<<<gLN, blk>>>(oa, nullptr, valid_a, fln_g, fln_b, xn);
    gemm_f2_kernel<1><<<gW1, blk>>>(xn, w1, b1, hid, ROWS, HIDn, Dn);
    gemm_f2_kernel<0><<<gProj, blk>>>(hid, w2, b2, yb, ROWS, Dn, HIDn);
    mln_kernel<<<gLN, blk>>>(yb, oa, valid_a, flno_g, flno_b, out_a);

    // 6. FFN for b
    mln_kernel<<<gLN, blk>>>(ob, nullptr, valid_b, fln_g, fln_b, xn);
    gemm_f2_kernel<1><<<gW1, blk>>>(xn, w1, b1, hid, ROWS, HIDn, Dn);
    gemm_f2_kernel<0><<<gProj, blk>>>(hid, w2, b2, yb, ROWS, Dn, HIDn);
    mln_kernel<<<gLN, blk>>>(yb, ob, valid_b, flno_g, flno_b, out_b);
}